// round 13
// baseline (speedup 1.0000x reference)
#include <cuda_runtime.h>
#include <cstdint>

// sim[b,o] = sum_d |x[b,d] - c[o,d]|;  out[b,o] = beta[o] * (max(sim)*1.001 - sim[b,o])
// R13: min-identity  |a-b| = a + b - 2*min(a,b)  =>
//   sim[m,n] = Sx[m] + Sc[n] - 2 * sum_k min(x[m,k], c[n,k])
// min -> scalar FMNMX (alu pipe), accumulate packed add.f32x2 (fma pipe):
// 6 issues / 4 products vs 8 before. Geometry = R10 best (32x64, frag 4x4, grid 256).

#define BM 32
#define BN 64
#define KC 32
#define NQ (KC / 4)        // 8 float4 quads per chunk
#define W_DIST 1.001f

typedef unsigned long long u64;

__device__ int      g_max_bits = 0;   // sims > 0 -> int order == float order
__device__ unsigned g_count1   = 0;
__device__ unsigned g_count2   = 0;

__device__ __forceinline__ u64 addx2(u64 a, u64 b) {
    u64 r; asm("add.rn.f32x2 %0, %1, %2;" : "=l"(r) : "l"(a), "l"(b)); return r;
}
__device__ __forceinline__ float hsum2(u64 a) {
    float2 v = *reinterpret_cast<float2*>(&a);
    return v.x + v.y;
}

__global__ __launch_bounds__(128, 2) void rbf_fused_kernel(
    const float* __restrict__ x,
    const float* __restrict__ c,
    const float* __restrict__ beta,
    float* __restrict__ out,
    int DIN, int DOUT, unsigned NB)
{
    // [buf][quad][row(+1 f4 pad)] — STS.128 fill and LDS.128 reads conflict-free.
    __shared__ float4 xs[2][NQ][BM + 1];
    __shared__ float4 cs[2][NQ][BN + 1];
    __shared__ float  wmax[4];
    __shared__ float  s_gm;

    const int tid = threadIdx.x;
    const int bm = blockIdx.y;
    const int bn = blockIdx.x;
    const int tr = tid >> 4;           // 0..7  -> m = tr + 8*i  (i<4)
    const int tc = tid & 15;           // 0..15 -> n = tc + 16*j (j<4)

    u64 acc[4][4];                     // packed sums of min(x,c)
    u64 sx2[4], sc2[4];                // packed row/col sums
#pragma unroll
    for (int i = 0; i < 4; i++) { sx2[i] = 0ULL; sc2[i] = 0ULL;
#pragma unroll
        for (int j = 0; j < 4; j++) acc[i][j] = 0ULL; }

    // fill mapping: x tile 32 rows x 8 quads (2/thread); c tile 64 rows x 8 quads (4/thread)
    const int fq = tid & 7;
    const int fr = tid >> 3;
    const int qpr = DIN / 4;
    const float4* xg0 = reinterpret_cast<const float4*>(x) + (size_t)(bm * BM + fr)      * qpr + fq;
    const float4* xg1 = reinterpret_cast<const float4*>(x) + (size_t)(bm * BM + fr + 16) * qpr + fq;
    const float4* cg0 = reinterpret_cast<const float4*>(c) + (size_t)(bn * BN + fr)      * qpr + fq;
    const float4* cg1 = reinterpret_cast<const float4*>(c) + (size_t)(bn * BN + fr + 16) * qpr + fq;
    const float4* cg2 = reinterpret_cast<const float4*>(c) + (size_t)(bn * BN + fr + 32) * qpr + fq;
    const float4* cg3 = reinterpret_cast<const float4*>(c) + (size_t)(bn * BN + fr + 48) * qpr + fq;

    float4 vx0 = *xg0, vx1 = *xg1;
    float4 vc0 = *cg0, vc1 = *cg1, vc2 = *cg2, vc3 = *cg3;

    xs[0][fq][fr]      = vx0;
    xs[0][fq][fr + 16] = vx1;
    cs[0][fq][fr]      = vc0;
    cs[0][fq][fr + 16] = vc1;
    cs[0][fq][fr + 32] = vc2;
    cs[0][fq][fr + 48] = vc3;
    __syncthreads();

    const int nchunks = DIN / KC;      // 16
    for (int ch = 0; ch < nchunks; ch++) {
        const int pb = ch & 1;
        if (ch + 1 < nchunks) {        // register prefetch of next chunk
            const int off = (ch + 1) * NQ;
            vx0 = xg0[off]; vx1 = xg1[off];
            vc0 = cg0[off]; vc1 = cg1[off]; vc2 = cg2[off]; vc3 = cg3[off];
        }

#pragma unroll
        for (int p2 = 0; p2 < NQ; p2++) {      // one float4 = 4 k-elements
            float4 xa[4], cb[4];
#pragma unroll
            for (int i = 0; i < 4; i++) xa[i] = xs[pb][p2][tr + 8 * i];
#pragma unroll
            for (int j = 0; j < 4; j++) cb[j] = cs[pb][p2][tc + 16 * j];

            // packed row / col sums (cover full K across p2 and chunks)
#pragma unroll
            for (int i = 0; i < 4; i++) {
                const u64* au = reinterpret_cast<const u64*>(&xa[i]);
                sx2[i] = addx2(sx2[i], au[0]);
                sx2[i] = addx2(sx2[i], au[1]);
            }
#pragma unroll
            for (int j = 0; j < 4; j++) {
                const u64* bu = reinterpret_cast<const u64*>(&cb[j]);
                sc2[j] = addx2(sc2[j], bu[0]);
                sc2[j] = addx2(sc2[j], bu[1]);
            }

#pragma unroll
            for (int i = 0; i < 4; i++) {
#pragma unroll
                for (int j = 0; j < 4; j++) {
                    // 4x FMNMX (alu) + 2x packed accumulate (fma)
                    float2 m0, m1;
                    m0.x = fminf(xa[i].x, cb[j].x);
                    m0.y = fminf(xa[i].y, cb[j].y);
                    m1.x = fminf(xa[i].z, cb[j].z);
                    m1.y = fminf(xa[i].w, cb[j].w);
                    acc[i][j] = addx2(acc[i][j], *reinterpret_cast<u64*>(&m0));
                    acc[i][j] = addx2(acc[i][j], *reinterpret_cast<u64*>(&m1));
                }
            }
        }

        if (ch + 1 < nchunks) {
            const int nb = 1 - pb;
            xs[nb][fq][fr]      = vx0;
            xs[nb][fq][fr + 16] = vx1;
            cs[nb][fq][fr]      = vc0;
            cs[nb][fq][fr + 16] = vc1;
            cs[nb][fq][fr + 32] = vc2;
            cs[nb][fq][fr + 48] = vc3;
        }
        __syncthreads();
    }

    // ---- reconstruct sim = Sx + Sc - 2*sum(min), block max ----
    float sxv[4], scv[4];
#pragma unroll
    for (int i = 0; i < 4; i++) sxv[i] = hsum2(sx2[i]);
#pragma unroll
    for (int j = 0; j < 4; j++) scv[j] = hsum2(sc2[j]);

    float s[4][4];
    float tmax = -1e30f;
#pragma unroll
    for (int i = 0; i < 4; i++)
#pragma unroll
        for (int j = 0; j < 4; j++) {
            s[i][j] = sxv[i] + scv[j] - 2.0f * hsum2(acc[i][j]);
            tmax = fmaxf(tmax, s[i][j]);
        }
#pragma unroll
    for (int off = 16; off > 0; off >>= 1)
        tmax = fmaxf(tmax, __shfl_xor_sync(0xffffffffu, tmax, off));
    if ((tid & 31) == 0) wmax[tid >> 5] = tmax;
    __syncthreads();

    // beta load before the spin (latency hidden under barrier wait)
    float bet[4];
#pragma unroll
    for (int j = 0; j < 4; j++) bet[j] = beta[bn * BN + tc + 16 * j];

    // ---- grid barrier (all 256 CTAs co-resident: launch_bounds(128,2), 256 <= 2*148) ----
    if (tid == 0) {
        float bmx = fmaxf(fmaxf(wmax[0], wmax[1]), fmaxf(wmax[2], wmax[3]));
        atomicMax(&g_max_bits, __float_as_int(bmx));
        __threadfence();
        atomicAdd(&g_count1, 1u);
        while (*((volatile unsigned*)&g_count1) < NB) { __nanosleep(64); }
        __threadfence();
        s_gm = __int_as_float(*((volatile int*)&g_max_bits)) * W_DIST;
        unsigned old = atomicAdd(&g_count2, 1u);   // last consumer resets for next graph replay
        if (old == NB - 1u) {
            g_max_bits = 0;
            g_count1   = 0;
            g_count2   = 0;
        }
    }
    __syncthreads();
    const float gm = s_gm;

    // ---- epilogue from registers ----
#pragma unroll
    for (int i = 0; i < 4; i++) {
        const int row = bm * BM + tr + 8 * i;
        float* orow = out + (size_t)row * DOUT + bn * BN;
#pragma unroll
        for (int j = 0; j < 4; j++)
            orow[tc + 16 * j] = bet[j] * (gm - s[i][j]);
    }
}

extern "C" void kernel_launch(void* const* d_in, const int* in_sizes, int n_in,
                              void* d_out, int out_size)
{
    const float* x    = (const float*)d_in[0];
    const float* c    = (const float*)d_in[1];
    const float* beta = (const float*)d_in[2];
    float* out = (float*)d_out;

    const int DOUT = in_sizes[2];
    const int DIN  = in_sizes[1] / DOUT;
    const int B    = in_sizes[0] / DIN;

    dim3 grid(DOUT / BN, B / BM);            // 8 x 32 = 256
    const unsigned NB = grid.x * grid.y;
    rbf_fused_kernel<<<grid, 128>>>(x, c, beta, out, DIN, DOUT, NB);
}

// round 14
// speedup vs baseline: 1.0580x; 1.0580x over previous
#include <cuda_runtime.h>
#include <cstdint>

// sim[b,o] = sum_d |x[b,d] - c[o,d]|;  out[b,o] = beta[o] * (max(sim)*1.001 - sim[b,o])
// R14: pipe-balanced hybrid.
//  quads 0..5: min-identity, packed:  2x FMNMX(alu) + 1x add.f32x2(fma) per 2 elems
//  quads 6..7: direct scalar:         FFMA(c,-1imm,x) rt1 + FADD(acc,|d|) rt2  (fma only)
//  -> both pipes ~1.5 busy-cyc/element (was alu 2.0 max).
// Row/col sums for the identity computed COOPERATIVELY (96 owner threads, 12 addx2/chunk)
// instead of redundantly in the inner loop (-116 fma instr/chunk/thread).
// Geometry = best known: 32x64 tiles, frag 4x4, 128 thr, grid 256, grid barrier.

#define BM 32
#define BN 64
#define KC 32
#define NQ (KC / 4)        // 8 float4 quads per chunk
#define NMINQ 6            // quads 0..5 via min-identity; 6..7 direct
#define W_DIST 1.001f

typedef unsigned long long u64;

__device__ int      g_max_bits = 0;   // sims > 0 -> int order == float order
__device__ unsigned g_count1   = 0;
__device__ unsigned g_count2   = 0;

__device__ __forceinline__ u64 addx2(u64 a, u64 b) {
    u64 r; asm("add.rn.f32x2 %0, %1, %2;" : "=l"(r) : "l"(a), "l"(b)); return r;
}
__device__ __forceinline__ float hsum2(u64 a) {
    float2 v = *reinterpret_cast<float2*>(&a);
    return v.x + v.y;
}
// x - c as FFMA(c, -1.0 imm, x): src1-imm form, rt_SMSP = 1
__device__ __forceinline__ float fnegma(float c, float x) {
    float r; asm("fma.rn.f32 %0, %1, 0fBF800000, %2;" : "=f"(r) : "f"(c), "f"(x)); return r;
}

__global__ __launch_bounds__(128, 2) void rbf_fused_kernel(
    const float* __restrict__ x,
    const float* __restrict__ c,
    const float* __restrict__ beta,
    float* __restrict__ out,
    int DIN, int DOUT, unsigned NB)
{
    // [buf][quad][row(+1 f4 pad)] — STS.128 fill and LDS.128 reads conflict-free.
    __shared__ float4 xs[2][NQ][BM + 1];
    __shared__ float4 cs[2][NQ][BN + 1];
    __shared__ float  rs[BM + BN];     // row sums: [0..31]=Sx rows, [32..95]=Sc rows (min-quads only)
    __shared__ float  wmax[4];
    __shared__ float  s_gm;

    const int tid = threadIdx.x;
    const int bm = blockIdx.y;
    const int bn = blockIdx.x;
    const int tr = tid >> 4;           // 0..7  -> m = tr + 8*i  (i<4)
    const int tc = tid & 15;           // 0..15 -> n = tc + 16*j (j<4)

    u64   accM[4][4];                  // packed sums of min(x,c) over min-quads
    float accD[4][4];                  // scalar sums of |x-c| over direct-quads
    u64   rowAcc = 0ULL;               // cooperative row-sum partial (owner threads)
#pragma unroll
    for (int i = 0; i < 4; i++)
#pragma unroll
        for (int j = 0; j < 4; j++) { accM[i][j] = 0ULL; accD[i][j] = 0.0f; }

    // fill mapping: x tile 32 rows x 8 quads (2/thread); c tile 64 rows x 8 quads (4/thread)
    const int fq = tid & 7;
    const int fr = tid >> 3;
    const int qpr = DIN / 4;
    const float4* xg0 = reinterpret_cast<const float4*>(x) + (size_t)(bm * BM + fr)      * qpr + fq;
    const float4* xg1 = reinterpret_cast<const float4*>(x) + (size_t)(bm * BM + fr + 16) * qpr + fq;
    const float4* cg0 = reinterpret_cast<const float4*>(c) + (size_t)(bn * BN + fr)      * qpr + fq;
    const float4* cg1 = reinterpret_cast<const float4*>(c) + (size_t)(bn * BN + fr + 16) * qpr + fq;
    const float4* cg2 = reinterpret_cast<const float4*>(c) + (size_t)(bn * BN + fr + 32) * qpr + fq;
    const float4* cg3 = reinterpret_cast<const float4*>(c) + (size_t)(bn * BN + fr + 48) * qpr + fq;

    float4 vx0 = *xg0, vx1 = *xg1;
    float4 vc0 = *cg0, vc1 = *cg1, vc2 = *cg2, vc3 = *cg3;

    xs[0][fq][fr]      = vx0;
    xs[0][fq][fr + 16] = vx1;
    cs[0][fq][fr]      = vc0;
    cs[0][fq][fr + 16] = vc1;
    cs[0][fq][fr + 32] = vc2;
    cs[0][fq][fr + 48] = vc3;
    __syncthreads();

    const int nchunks = DIN / KC;      // 16
    for (int ch = 0; ch < nchunks; ch++) {
        const int pb = ch & 1;
        if (ch + 1 < nchunks) {        // register prefetch of next chunk
            const int off = (ch + 1) * NQ;
            vx0 = xg0[off]; vx1 = xg1[off];
            vc0 = cg0[off]; vc1 = cg1[off]; vc2 = cg2[off]; vc3 = cg3[off];
        }

#pragma unroll
        for (int p2 = 0; p2 < NQ; p2++) {      // one float4 = 4 k-elements
            float4 xa[4], cb[4];
#pragma unroll
            for (int i = 0; i < 4; i++) xa[i] = xs[pb][p2][tr + 8 * i];
#pragma unroll
            for (int j = 0; j < 4; j++) cb[j] = cs[pb][p2][tc + 16 * j];

            if (p2 < NMINQ) {
                // ---- min-identity path: 4 FMNMX (alu) + 2 packed adds (fma) ----
#pragma unroll
                for (int i = 0; i < 4; i++)
#pragma unroll
                    for (int j = 0; j < 4; j++) {
                        float2 m0, m1;
                        m0.x = fminf(xa[i].x, cb[j].x);
                        m0.y = fminf(xa[i].y, cb[j].y);
                        m1.x = fminf(xa[i].z, cb[j].z);
                        m1.y = fminf(xa[i].w, cb[j].w);
                        accM[i][j] = addx2(accM[i][j], *reinterpret_cast<u64*>(&m0));
                        accM[i][j] = addx2(accM[i][j], *reinterpret_cast<u64*>(&m1));
                    }
            } else {
                // ---- direct path: FFMA-imm diff (rt1) + FADD with |.| modifier (rt2), fma pipe only ----
#pragma unroll
                for (int i = 0; i < 4; i++)
#pragma unroll
                    for (int j = 0; j < 4; j++) {
                        float a = accD[i][j];
                        a += fabsf(fnegma(cb[j].x, xa[i].x));
                        a += fabsf(fnegma(cb[j].y, xa[i].y));
                        a += fabsf(fnegma(cb[j].z, xa[i].z));
                        a += fabsf(fnegma(cb[j].w, xa[i].w));
                        accD[i][j] = a;
                    }
            }
        }

        // ---- cooperative row/col sums over min-quads (owner threads 0..95) ----
        if (tid < BM + BN) {
            if (tid < BM) {
#pragma unroll
                for (int q = 0; q < NMINQ; q++) {
                    float4 v = xs[pb][q][tid];
                    const u64* p = reinterpret_cast<const u64*>(&v);
                    rowAcc = addx2(rowAcc, p[0]);
                    rowAcc = addx2(rowAcc, p[1]);
                }
            } else {
#pragma unroll
                for (int q = 0; q < NMINQ; q++) {
                    float4 v = cs[pb][q][tid - BM];
                    const u64* p = reinterpret_cast<const u64*>(&v);
                    rowAcc = addx2(rowAcc, p[0]);
                    rowAcc = addx2(rowAcc, p[1]);
                }
            }
        }

        if (ch + 1 < nchunks) {        // store prefetched chunk into the other buffer
            const int nb = 1 - pb;
            xs[nb][fq][fr]      = vx0;
            xs[nb][fq][fr + 16] = vx1;
            cs[nb][fq][fr]      = vc0;
            cs[nb][fq][fr + 16] = vc1;
            cs[nb][fq][fr + 32] = vc2;
            cs[nb][fq][fr + 48] = vc3;
        }
        __syncthreads();
    }

    // publish row/col sums
    if (tid < BM + BN) rs[tid] = hsum2(rowAcc);
    __syncthreads();

    // ---- reconstruct sim = Sx + Sc - 2*sum(min) + sum_direct ----
    float sxv[4], scv[4];
#pragma unroll
    for (int i = 0; i < 4; i++) sxv[i] = rs[tr + 8 * i];
#pragma unroll
    for (int j = 0; j < 4; j++) scv[j] = rs[BM + tc + 16 * j];

    float s[4][4];
    float tmax = -1e30f;
#pragma unroll
    for (int i = 0; i < 4; i++)
#pragma unroll
        for (int j = 0; j < 4; j++) {
            s[i][j] = sxv[i] + scv[j] - 2.0f * hsum2(accM[i][j]) + accD[i][j];
            tmax = fmaxf(tmax, s[i][j]);
        }
#pragma unroll
    for (int off = 16; off > 0; off >>= 1)
        tmax = fmaxf(tmax, __shfl_xor_sync(0xffffffffu, tmax, off));
    if ((tid & 31) == 0) wmax[tid >> 5] = tmax;
    __syncthreads();

    // beta load before the spin (latency hidden under barrier wait)
    float bet[4];
#pragma unroll
    for (int j = 0; j < 4; j++) bet[j] = beta[bn * BN + tc + 16 * j];

    // ---- grid barrier (all 256 CTAs co-resident: launch_bounds(128,2), 256 <= 2*148) ----
    if (tid == 0) {
        float bmx = fmaxf(fmaxf(wmax[0], wmax[1]), fmaxf(wmax[2], wmax[3]));
        atomicMax(&g_max_bits, __float_as_int(bmx));
        __threadfence();
        atomicAdd(&g_count1, 1u);
        while (*((volatile unsigned*)&g_count1) < NB) { __nanosleep(64); }
        __threadfence();
        s_gm = __int_as_float(*((volatile int*)&g_max_bits)) * W_DIST;
        unsigned old = atomicAdd(&g_count2, 1u);   // last consumer resets for next graph replay
        if (old == NB - 1u) {
            g_max_bits = 0;
            g_count1   = 0;
            g_count2   = 0;
        }
    }
    __syncthreads();
    const float gm = s_gm;

    // ---- epilogue from registers ----
#pragma unroll
    for (int i = 0; i < 4; i++) {
        const int row = bm * BM + tr + 8 * i;
        float* orow = out + (size_t)row * DOUT + bn * BN;
#pragma unroll
        for (int j = 0; j < 4; j++)
            orow[tc + 16 * j] = bet[j] * (gm - s[i][j]);
    }
}

extern "C" void kernel_launch(void* const* d_in, const int* in_sizes, int n_in,
                              void* d_out, int out_size)
{
    const float* x    = (const float*)d_in[0];
    const float* c    = (const float*)d_in[1];
    const float* beta = (const float*)d_in[2];
    float* out = (float*)d_out;

    const int DOUT = in_sizes[2];
    const int DIN  = in_sizes[1] / DOUT;
    const int B    = in_sizes[0] / DIN;

    dim3 grid(DOUT / BN, B / BM);            // 8 x 32 = 256
    const unsigned NB = grid.x * grid.y;
    rbf_fused_kernel<<<grid, 128>>>(x, c, beta, out, DIN, DOUT, NB);
}